// round 1
// baseline (speedup 1.0000x reference)
#include <cuda_runtime.h>
#include <cstdint>

#define N_NODES 100000
#define D 64

// Scratch (no allocation allowed): fused weight + support matrix.
__device__ float g_wsum[D * D];
__device__ float g_support[(size_t)N_NODES * D];

// ---------------------------------------------------------------------------
// Kernel 0: W_sum = W_own + W_nbr + W_temp   (64x64, one block)
// ---------------------------------------------------------------------------
__global__ void wsum_kernel(const float* __restrict__ wo,
                            const float* __restrict__ wn,
                            const float* __restrict__ wt) {
    for (int i = threadIdx.x; i < D * D; i += blockDim.x)
        g_wsum[i] = wo[i] + wn[i] + wt[i];
}

// ---------------------------------------------------------------------------
// Kernel 1: support = x @ W_sum   ([N,64] @ [64,64])
// Block: 256 threads (16x16). Tile: 64 rows x 64 cols. Each thread: 4x4.
// ---------------------------------------------------------------------------
#define XS_STRIDE 68  // 64+4: multiple of 4 (float4 stores OK), kills bank conflicts

__global__ __launch_bounds__(256) void gemm64_kernel(const float* __restrict__ x,
                                                     float* __restrict__ support,
                                                     int nrows) {
    __shared__ float Xs[64][XS_STRIDE];
    __shared__ float Ws[64][64];

    const int tx = threadIdx.x & 15;   // col group 0..15
    const int ty = threadIdx.x >> 4;   // row group 0..15
    const int tid = threadIdx.x;
    const int row0 = blockIdx.x * 64;

    // Load W (4096 floats, 16 per thread, float4)
    {
        const float4* wsrc = (const float4*)g_wsum;
        float4* wdst = (float4*)&Ws[0][0];
        #pragma unroll
        for (int i = 0; i < 4; i++)
            wdst[tid + 256 * i] = wsrc[tid + 256 * i];
    }

    // Load X tile: 64 rows x 64 cols. 16 float4s per thread.
    // thread tid loads float4 j: element index = tid*16 + j*4 within the tile
    {
        #pragma unroll
        for (int i = 0; i < 4; i++) {
            int elem = (tid + 256 * i) * 4;        // 0..16380 step 4
            int r = elem >> 6;                     // /64
            int c = elem & 63;
            int gr = row0 + r;
            float4 v = make_float4(0.f, 0.f, 0.f, 0.f);
            if (gr < nrows) v = *(const float4*)(x + (size_t)gr * D + c);
            *(float4*)&Xs[r][c] = v;
        }
    }
    __syncthreads();

    float acc[4][4];
    #pragma unroll
    for (int i = 0; i < 4; i++)
        #pragma unroll
        for (int j = 0; j < 4; j++) acc[i][j] = 0.f;

    #pragma unroll
    for (int k = 0; k < 64; k++) {
        float4 b = *(const float4*)&Ws[k][tx * 4];
        float a0 = Xs[ty * 4 + 0][k];
        float a1 = Xs[ty * 4 + 1][k];
        float a2 = Xs[ty * 4 + 2][k];
        float a3 = Xs[ty * 4 + 3][k];
        acc[0][0] += a0 * b.x; acc[0][1] += a0 * b.y; acc[0][2] += a0 * b.z; acc[0][3] += a0 * b.w;
        acc[1][0] += a1 * b.x; acc[1][1] += a1 * b.y; acc[1][2] += a1 * b.z; acc[1][3] += a1 * b.w;
        acc[2][0] += a2 * b.x; acc[2][1] += a2 * b.y; acc[2][2] += a2 * b.z; acc[2][3] += a2 * b.w;
        acc[3][0] += a3 * b.x; acc[3][1] += a3 * b.y; acc[3][2] += a3 * b.z; acc[3][3] += a3 * b.w;
    }

    #pragma unroll
    for (int i = 0; i < 4; i++) {
        int gr = row0 + ty * 4 + i;
        if (gr < nrows) {
            float4 v = make_float4(acc[i][0], acc[i][1], acc[i][2], acc[i][3]);
            *(float4*)(support + (size_t)gr * D + tx * 4) = v;
        }
    }
}

// ---------------------------------------------------------------------------
// Kernel 2: out[n][c] = bias[c]  (initialize output; also applies bias)
// ---------------------------------------------------------------------------
__global__ __launch_bounds__(256) void bias_init_kernel(float* __restrict__ out,
                                                        const float* __restrict__ bias,
                                                        int n_f4) {
    int i = blockIdx.x * blockDim.x + threadIdx.x;
    if (i >= n_f4) return;
    int c4 = i & 15;  // (i*4) % 64 / 4
    float4 b = __ldg(((const float4*)bias) + c4);
    ((float4*)out)[i] = b;
}

// ---------------------------------------------------------------------------
// Kernel 3: scatter-add  out[row] += val * support[col]
// 2 edges per warp: lanes 0-15 -> edge e, lanes 16-31 -> edge e+1.
// Each lane handles one float4 (16 lanes * 16B = 256B = one 64-float row).
// red.global.add.v4.f32: no-return atomic, min instruction count.
// ---------------------------------------------------------------------------
__global__ __launch_bounds__(256) void scatter_kernel(const int* __restrict__ erow,
                                                      const int* __restrict__ ecol,
                                                      const float* __restrict__ eval,
                                                      const float* __restrict__ support,
                                                      float* __restrict__ out,
                                                      int E) {
    const int lane = threadIdx.x & 31;
    const int sub = lane & 15;          // float4 index within the row
    const int half = lane >> 4;         // which of the 2 edges
    const int warp = (blockIdx.x * blockDim.x + threadIdx.x) >> 5;
    const int nwarps = (gridDim.x * blockDim.x) >> 5;

    for (int e = warp * 2 + half; e < E; e += nwarps * 2) {
        int r = __ldg(erow + e);
        int c = __ldg(ecol + e);
        float v = __ldg(eval + e);

        float4 s = __ldg((const float4*)(support + (size_t)c * D) + sub);
        float4 m = make_float4(v * s.x, v * s.y, v * s.z, v * s.w);
        float* dst = out + (size_t)r * D + sub * 4;
        asm volatile("red.global.add.v4.f32 [%0], {%1, %2, %3, %4};"
                     :: "l"(dst), "f"(m.x), "f"(m.y), "f"(m.z), "f"(m.w)
                     : "memory");
    }
}

// ---------------------------------------------------------------------------
// Launch
// Inputs: 0:x 1:edge_rows 2:edge_cols 3:edge_vals 4:W_own 5:W_nbr 6:W_temp 7:bias
// ---------------------------------------------------------------------------
extern "C" void kernel_launch(void* const* d_in, const int* in_sizes, int n_in,
                              void* d_out, int out_size) {
    const float* x    = (const float*)d_in[0];
    const int*   erow = (const int*)d_in[1];
    const int*   ecol = (const int*)d_in[2];
    const float* eval = (const float*)d_in[3];
    const float* wo   = (const float*)d_in[4];
    const float* wn   = (const float*)d_in[5];
    const float* wt   = (const float*)d_in[6];
    const float* bias = (const float*)d_in[7];
    float* out = (float*)d_out;

    const int nrows = in_sizes[0] / D;   // 100000
    const int E = in_sizes[1];           // 1.6M

    float* support;
    cudaGetSymbolAddress((void**)&support, g_support);

    // K0: fuse weights
    wsum_kernel<<<1, 256>>>(wo, wn, wt);

    // K1: GEMM support = x @ wsum
    gemm64_kernel<<<(nrows + 63) / 64, 256>>>(x, support, nrows);

    // K2: init out with bias
    int n_f4 = out_size / 4;
    bias_init_kernel<<<(n_f4 + 255) / 256, 256>>>(out, bias, n_f4);

    // K3: scatter-add over edges
    scatter_kernel<<<2048, 256>>>(erow, ecol, eval, support, out, E);
}

// round 2
// speedup vs baseline: 1.0961x; 1.0961x over previous
#include <cuda_runtime.h>
#include <cuda_fp16.h>
#include <cstdint>

#define N_NODES 100000
#define D 64

// Scratch (no allocation allowed): fused weight + fp16 support matrix.
__device__ float  g_wsum[D * D];
__device__ __half g_support[(size_t)N_NODES * D];

// ---------------------------------------------------------------------------
// Kernel 0: W_sum = W_own + W_nbr + W_temp   (64x64, one block)
// ---------------------------------------------------------------------------
__global__ void wsum_kernel(const float* __restrict__ wo,
                            const float* __restrict__ wn,
                            const float* __restrict__ wt) {
    for (int i = threadIdx.x; i < D * D; i += blockDim.x)
        g_wsum[i] = wo[i] + wn[i] + wt[i];
}

// ---------------------------------------------------------------------------
// Kernel 1: support = fp16(x @ W_sum)   ([N,64] @ [64,64])
// Block: 256 threads (16x16). Tile: 64 rows x 64 cols. Each thread: 4x4.
// ---------------------------------------------------------------------------
#define XS_STRIDE 68  // 64+4: float4-store friendly, kills bank conflicts

__global__ __launch_bounds__(256) void gemm64_kernel(const float* __restrict__ x,
                                                     __half* __restrict__ support,
                                                     int nrows) {
    __shared__ float Xs[64][XS_STRIDE];
    __shared__ float Ws[64][64];

    const int tx = threadIdx.x & 15;   // col group 0..15
    const int ty = threadIdx.x >> 4;   // row group 0..15
    const int tid = threadIdx.x;
    const int row0 = blockIdx.x * 64;

    // Load W (4096 floats, 16 per thread, float4)
    {
        const float4* wsrc = (const float4*)g_wsum;
        float4* wdst = (float4*)&Ws[0][0];
        #pragma unroll
        for (int i = 0; i < 4; i++)
            wdst[tid + 256 * i] = wsrc[tid + 256 * i];
    }

    // Load X tile: 64 rows x 64 cols, 4 float4s per thread.
    {
        #pragma unroll
        for (int i = 0; i < 4; i++) {
            int elem = (tid + 256 * i) * 4;        // 0..16380 step 4
            int r = elem >> 6;                     // /64
            int c = elem & 63;
            int gr = row0 + r;
            float4 v = make_float4(0.f, 0.f, 0.f, 0.f);
            if (gr < nrows) v = *(const float4*)(x + (size_t)gr * D + c);
            *(float4*)&Xs[r][c] = v;
        }
    }
    __syncthreads();

    float acc[4][4];
    #pragma unroll
    for (int i = 0; i < 4; i++)
        #pragma unroll
        for (int j = 0; j < 4; j++) acc[i][j] = 0.f;

    #pragma unroll
    for (int k = 0; k < 64; k++) {
        float4 b = *(const float4*)&Ws[k][tx * 4];
        float a0 = Xs[ty * 4 + 0][k];
        float a1 = Xs[ty * 4 + 1][k];
        float a2 = Xs[ty * 4 + 2][k];
        float a3 = Xs[ty * 4 + 3][k];
        acc[0][0] += a0 * b.x; acc[0][1] += a0 * b.y; acc[0][2] += a0 * b.z; acc[0][3] += a0 * b.w;
        acc[1][0] += a1 * b.x; acc[1][1] += a1 * b.y; acc[1][2] += a1 * b.z; acc[1][3] += a1 * b.w;
        acc[2][0] += a2 * b.x; acc[2][1] += a2 * b.y; acc[2][2] += a2 * b.z; acc[2][3] += a2 * b.w;
        acc[3][0] += a3 * b.x; acc[3][1] += a3 * b.y; acc[3][2] += a3 * b.z; acc[3][3] += a3 * b.w;
    }

    #pragma unroll
    for (int i = 0; i < 4; i++) {
        int gr = row0 + ty * 4 + i;
        if (gr < nrows) {
            __half2 p0 = __floats2half2_rn(acc[i][0], acc[i][1]);
            __half2 p1 = __floats2half2_rn(acc[i][2], acc[i][3]);
            __half2* dst = (__half2*)(support + (size_t)gr * D + tx * 4);
            dst[0] = p0;
            dst[1] = p1;
        }
    }
}

// ---------------------------------------------------------------------------
// Kernel 2: out[n][c] = bias[c]  (initialize output; also applies bias)
// ---------------------------------------------------------------------------
__global__ __launch_bounds__(256) void bias_init_kernel(float* __restrict__ out,
                                                        const float* __restrict__ bias,
                                                        int n_f4) {
    int i = blockIdx.x * blockDim.x + threadIdx.x;
    if (i >= n_f4) return;
    int c4 = i & 15;
    float4 b = __ldg(((const float4*)bias) + c4);
    ((float4*)out)[i] = b;
}

// ---------------------------------------------------------------------------
// Kernel 3: scatter-add  out[row] += val * fp16(support[col])
// 2 edges per warp per slot (half-warps), UNROLL=4 slots in flight:
// all index loads, then all gathers (8B/lane fp16), then all REDs (fp32 v4).
// ---------------------------------------------------------------------------
#define UNROLL 4

__global__ __launch_bounds__(256) void scatter_kernel(const int* __restrict__ erow,
                                                      const int* __restrict__ ecol,
                                                      const float* __restrict__ eval,
                                                      const __half* __restrict__ support,
                                                      float* __restrict__ out,
                                                      int E) {
    const int lane = threadIdx.x & 31;
    const int sub = lane & 15;          // 8-byte chunk within the 128B fp16 row
    const int half_id = lane >> 4;      // which of the 2 edges in this slot
    const int warp = (blockIdx.x * blockDim.x + threadIdx.x) >> 5;
    const int nwarps = (gridDim.x * blockDim.x) >> 5;
    const int stride = nwarps * 2 * UNROLL;

    for (int base = warp * 2 * UNROLL + half_id; base < E; base += stride) {
        int   r[UNROLL], c[UNROLL];
        float v[UNROLL];
        bool  ok[UNROLL];

        #pragma unroll
        for (int j = 0; j < UNROLL; j++) {
            int e = base + 2 * j;
            ok[j] = (e < E);
            r[j] = 0; c[j] = 0; v[j] = 0.f;
            if (ok[j]) {
                r[j] = __ldg(erow + e);
                c[j] = __ldg(ecol + e);
                v[j] = __ldg(eval + e);
            }
        }

        uint2 raw[UNROLL];
        #pragma unroll
        for (int j = 0; j < UNROLL; j++) {
            if (ok[j])
                raw[j] = __ldg((const uint2*)(support + (size_t)c[j] * D) + sub);
        }

        #pragma unroll
        for (int j = 0; j < UNROLL; j++) {
            if (!ok[j]) continue;
            __half2 h0 = *(__half2*)&raw[j].x;
            __half2 h1 = *(__half2*)&raw[j].y;
            float2 f0 = __half22float2(h0);
            float2 f1 = __half22float2(h1);
            float vj = v[j];
            float* dst = out + (size_t)r[j] * D + sub * 4;
            asm volatile("red.global.add.v4.f32 [%0], {%1, %2, %3, %4};"
                         :: "l"(dst), "f"(vj * f0.x), "f"(vj * f0.y),
                            "f"(vj * f1.x), "f"(vj * f1.y)
                         : "memory");
        }
    }
}

// ---------------------------------------------------------------------------
// Launch
// Inputs: 0:x 1:edge_rows 2:edge_cols 3:edge_vals 4:W_own 5:W_nbr 6:W_temp 7:bias
// ---------------------------------------------------------------------------
extern "C" void kernel_launch(void* const* d_in, const int* in_sizes, int n_in,
                              void* d_out, int out_size) {
    const float* x    = (const float*)d_in[0];
    const int*   erow = (const int*)d_in[1];
    const int*   ecol = (const int*)d_in[2];
    const float* eval = (const float*)d_in[3];
    const float* wo   = (const float*)d_in[4];
    const float* wn   = (const float*)d_in[5];
    const float* wt   = (const float*)d_in[6];
    const float* bias = (const float*)d_in[7];
    float* out = (float*)d_out;

    const int nrows = in_sizes[0] / D;   // 100000
    const int E = in_sizes[1];           // 1.6M

    __half* support;
    cudaGetSymbolAddress((void**)&support, g_support);

    // K0: fuse weights
    wsum_kernel<<<1, 256>>>(wo, wn, wt);

    // K1: GEMM support = fp16(x @ wsum)
    gemm64_kernel<<<(nrows + 63) / 64, 256>>>(x, support, nrows);

    // K2: init out with bias
    int n_f4 = out_size / 4;
    bias_init_kernel<<<(n_f4 + 255) / 256, 256>>>(out, bias, n_f4);

    // K3: scatter-add over edges
    scatter_kernel<<<2048, 256>>>(erow, ecol, eval, support, out, E);
}